// round 15
// baseline (speedup 1.0000x reference)
#include <cuda_runtime.h>
#include <cuda_fp16.h>
#include <math.h>
#include <stdint.h>

#define B_   4
#define T_   2048
#define D_   1024
#define H_   16
#define DH_  64
#define NTOK (B_ * T_)          // 8192
#define QKV_COLS (3 * D_)       // 3072

// ---------------------------------------------------------------------------
// fp16 global scratch (allocation-free rule: __device__ globals)
// ---------------------------------------------------------------------------
__device__ __half g_x_h[(size_t)NTOK * D_];
__device__ __half g_wqkv_h[(size_t)QKV_COLS * D_];
__device__ __half g_wout_h[(size_t)D_ * D_];
__device__ __half g_qkv_h[(size_t)NTOK * QKV_COLS];
__device__ __half g_attn_h[(size_t)NTOK * D_];

// ---------------------------------------------------------------------------
// helpers
// ---------------------------------------------------------------------------
__device__ __forceinline__ uint32_t su32(const void* p) {
    return (uint32_t)__cvta_generic_to_shared(p);
}
__device__ __forceinline__ void ldsm4(uint32_t* r, uint32_t a) {
    asm volatile("ldmatrix.sync.aligned.m8n8.x4.shared.b16 {%0,%1,%2,%3}, [%4];"
        : "=r"(r[0]), "=r"(r[1]), "=r"(r[2]), "=r"(r[3]) : "r"(a));
}
__device__ __forceinline__ void ldsm4t(uint32_t* r, uint32_t a) {
    asm volatile("ldmatrix.sync.aligned.m8n8.x4.trans.shared.b16 {%0,%1,%2,%3}, [%4];"
        : "=r"(r[0]), "=r"(r[1]), "=r"(r[2]), "=r"(r[3]) : "r"(a));
}
__device__ __forceinline__ void mmaf16(float* c, const uint32_t* a,
                                       uint32_t b0, uint32_t b1) {
    asm volatile(
        "mma.sync.aligned.m16n8k16.row.col.f32.f16.f16.f32 "
        "{%0,%1,%2,%3},{%4,%5,%6,%7},{%8,%9},{%0,%1,%2,%3};"
        : "+f"(c[0]), "+f"(c[1]), "+f"(c[2]), "+f"(c[3])
        : "r"(a[0]), "r"(a[1]), "r"(a[2]), "r"(a[3]), "r"(b0), "r"(b1));
}
__device__ __forceinline__ uint32_t pkh(float x, float y) {
    __half2 t = __floats2half2_rn(x, y);
    return *reinterpret_cast<uint32_t*>(&t);
}
__device__ __forceinline__ float ex2(float x) {
    float r;
    asm("ex2.approx.f32 %0, %1;" : "=f"(r) : "f"(x));
    return r;
}
__device__ __forceinline__ uint32_t hex2(uint32_t a) {
    uint32_t r;
    asm("ex2.approx.f16x2 %0, %1;" : "=r"(r) : "r"(a));
    return r;
}
__device__ __forceinline__ float2 h2f2(uint32_t a) {
    __half2 t = *reinterpret_cast<__half2*>(&a);
    return __half22float2(t);
}
__device__ __forceinline__ void cpa16(uint32_t s, const void* g) {
    asm volatile("cp.async.cg.shared.global [%0], [%1], 16;" :: "r"(s), "l"(g));
}
#define CP_COMMIT() asm volatile("cp.async.commit_group;" ::: "memory")
#define CP_WAIT(n)  asm volatile("cp.async.wait_group %0;" :: "n"(n) : "memory")

// PDL intrinsics (base sm_90 PTX; no 'a' suffix needed)
__device__ __forceinline__ void gdc_launch() {
    asm volatile("griddepcontrol.launch_dependents;");
}
__device__ __forceinline__ void gdc_wait() {
    asm volatile("griddepcontrol.wait;" ::: "memory");
}

// ---------------------------------------------------------------------------
// merged presplit: fp32 -> fp16 for x, w_qkv, w_out in one launch
// ---------------------------------------------------------------------------
#define N4_X  (NTOK * D_ / 4)
#define N4_WQ (QKV_COLS * D_ / 4)
#define N4_WO (D_ * D_ / 4)

__global__ void presingle_all(const float* __restrict__ x,
                              const float* __restrict__ wq,
                              const float* __restrict__ wo,
                              __half* __restrict__ xh,
                              __half* __restrict__ wqh,
                              __half* __restrict__ woh)
{
    const int total = N4_X + N4_WQ + N4_WO;
    int i = blockIdx.x * blockDim.x + threadIdx.x;
    const int stride = gridDim.x * blockDim.x;
    for (; i < total; i += stride) {
        const float* src;
        __half* dst;
        int j = i;
        if (j < N4_X)                { src = x;  dst = xh; }
        else if ((j -= N4_X) < N4_WQ){ src = wq; dst = wqh; }
        else                         { j -= N4_WQ; src = wo; dst = woh; }
        float4 v = ((const float4*)src)[j];
        ((uint2*)dst)[j] = make_uint2(pkh(v.x, v.y), pkh(v.z, v.w));
    }
}

// ---------------------------------------------------------------------------
// fp16 GEMM (R12 math, + PDL protocol):
//   gdc_launch at entry (all CTAs placed -> successor may launch),
//   gdc_wait before first dependent-data read iff do_wait != 0.
// BM=BN=128, BK=32, 128 threads (4 warps 2x2, warp tile 64x64).
// ---------------------------------------------------------------------------
#define GST 40
#define GARR (128 * GST * 2)
#define GSTAGE (2 * GARR)
#define NSTG 4

template<bool WRITE_HALF>
__global__ __launch_bounds__(128, 2)
void gemm_f16(const __half* __restrict__ Ahg, const __half* __restrict__ Bhg,
              const float* __restrict__ bias,
              float* __restrict__ Cf, __half* __restrict__ Ch,
              int Ntot, int K, int do_wait)
{
    extern __shared__ char dsm[];

    gdc_launch();
    if (do_wait) gdc_wait();

    const int tid = threadIdx.x, lane = tid & 31, wid = tid >> 5;
    const int wm = wid & 1, wn = wid >> 1;
    const int row0 = blockIdx.y * 128, col0 = blockIdx.x * 128;

    float acc[4][8][4];
#pragma unroll
    for (int mt = 0; mt < 4; mt++)
#pragma unroll
        for (int nt = 0; nt < 8; nt++)
#pragma unroll
            for (int i = 0; i < 4; i++) acc[mt][nt][i] = 0.f;

    auto prefetch = [&](int it) {
        char* base = dsm + (it & (NSTG - 1)) * GSTAGE;
#pragma unroll
        for (int i = 0; i < 4; i++) {
            const int id = tid + i * 128;
            const int r = id >> 2, c = id & 3;
            const uint32_t so = r * 80 + c * 16;
            cpa16(su32(base + so),        Ahg + (size_t)(row0 + r) * K + it * 32 + c * 8);
            cpa16(su32(base + GARR + so), Bhg + (size_t)(col0 + r) * K + it * 32 + c * 8);
        }
    };

    const int nit = K / 32;
#pragma unroll
    for (int it = 0; it < NSTG - 1; it++) { prefetch(it); CP_COMMIT(); }

    const uint32_t la = ((lane & 15) * GST + ((lane >> 4) << 3)) * 2;
    const uint32_t awo = wm * 64 * GST * 2 + la;
    const uint32_t bwo = GARR + wn * 64 * GST * 2 + la;

    CP_WAIT(NSTG - 2);
    __syncthreads();

    uint32_t fa[2][4][4], fb[2][4][4];
    {
        const uint32_t sbase = su32(dsm);
#pragma unroll
        for (int t = 0; t < 4; t++) ldsm4(fa[0][t], sbase + awo + t * 16 * GST * 2);
#pragma unroll
        for (int t = 0; t < 4; t++) ldsm4(fb[0][t], sbase + bwo + t * 16 * GST * 2);
    }

    for (int it = 0; it < nit; it++) {
        const uint32_t sbase = su32(dsm + (it & (NSTG - 1)) * GSTAGE);

#pragma unroll
        for (int t = 0; t < 4; t++) ldsm4(fa[1][t], sbase + awo + t * 16 * GST * 2 + 32);
#pragma unroll
        for (int t = 0; t < 4; t++) ldsm4(fb[1][t], sbase + bwo + t * 16 * GST * 2 + 32);

#pragma unroll
        for (int mt = 0; mt < 4; mt++)
#pragma unroll
            for (int np = 0; np < 4; np++) {
                mmaf16(acc[mt][np * 2],     fa[0][mt], fb[0][np][0], fb[0][np][2]);
                mmaf16(acc[mt][np * 2 + 1], fa[0][mt], fb[0][np][1], fb[0][np][3]);
            }

        if (it + NSTG - 1 < nit) prefetch(it + NSTG - 1);
        CP_COMMIT();
        CP_WAIT(NSTG - 2);
        __syncthreads();

        if (it + 1 < nit) {
            const uint32_t sb2 = su32(dsm + ((it + 1) & (NSTG - 1)) * GSTAGE);
#pragma unroll
            for (int t = 0; t < 4; t++) ldsm4(fa[0][t], sb2 + awo + t * 16 * GST * 2);
#pragma unroll
            for (int t = 0; t < 4; t++) ldsm4(fb[0][t], sb2 + bwo + t * 16 * GST * 2);
        }

#pragma unroll
        for (int mt = 0; mt < 4; mt++)
#pragma unroll
            for (int np = 0; np < 4; np++) {
                mmaf16(acc[mt][np * 2],     fa[1][mt], fb[1][np][0], fb[1][np][2]);
                mmaf16(acc[mt][np * 2 + 1], fa[1][mt], fb[1][np][1], fb[1][np][3]);
            }
    }

    const int g = lane >> 2, tq = lane & 3;
#pragma unroll
    for (int mt = 0; mt < 4; mt++) {
        const int r = row0 + wm * 64 + mt * 16 + g;
#pragma unroll
        for (int nt = 0; nt < 8; nt++) {
            const int c = col0 + wn * 64 + nt * 8 + tq * 2;
            float2 bi = *(const float2*)(bias + c);
            const float f0 = acc[mt][nt][0] + bi.x, f1 = acc[mt][nt][1] + bi.y;
            const float f2 = acc[mt][nt][2] + bi.x, f3 = acc[mt][nt][3] + bi.y;
            if (WRITE_HALF) {
                *(uint32_t*)&Ch[(size_t)r * Ntot + c]       = pkh(f0, f1);
                *(uint32_t*)&Ch[(size_t)(r + 8) * Ntot + c] = pkh(f2, f3);
            } else {
                *(float2*)(Cf + (size_t)r * Ntot + c)       = make_float2(f0, f1);
                *(float2*)(Cf + (size_t)(r + 8) * Ntot + c) = make_float2(f2, f3);
            }
        }
    }
}

// ---------------------------------------------------------------------------
// Flash attention (R12 math, + PDL: trigger at entry, wait before Q load).
// Grid: (T/128, H) per batch — batch via pointer offsets.
// ---------------------------------------------------------------------------
#define AST 72
#define AARR (128 * AST * 2)   // 18432 bytes per array
#define C2   0.1803368801f     // (1/sqrt(64)) * log2(e)

__global__ __launch_bounds__(256, 2)
void attn_f16(const __half* __restrict__ qkvh, __half* __restrict__ attnh)
{
    extern __shared__ char dsm[];   // K0 | K1 | V0 | V1

    gdc_launch();
    gdc_wait();                     // needs this batch's QKV complete

    const int tid = threadIdx.x, lane = tid & 31, wid = tid >> 5;
    const int h = blockIdx.y & 15;
    const int q0 = blockIdx.x * 128;

    const size_t hb = (size_t)h * DH_;
    const __half* qbh = qkvh + hb;
    const __half* kbh = qbh + D_;
    const __half* vbh = qbh + 2 * D_;

    auto loadTile = [&](const __half* src, char* dstbase, int row_off) {
#pragma unroll
        for (int i = 0; i < 4; i++) {
            const int id = tid + i * 256;
            const int r = id >> 3, c = id & 7;
            const uint32_t so = r * 144 + c * 16;
            const size_t g = (size_t)(row_off + r) * QKV_COLS + c * 8;
            cpa16(su32(dstbase + so), src + g);
        }
    };

    // ---- stage Q into K0, pull fragments ----
    loadTile(qbh, dsm, q0);
    CP_COMMIT(); CP_WAIT(0); __syncthreads();

    uint32_t qh[4][4];
    {
        const __half* Kh = (const __half*)dsm;
#pragma unroll
        for (int kc = 0; kc < 4; kc++) {
            const int rw = wid * 16 + (lane & 15);
            const int cl = kc * 16 + ((lane >> 4) << 3);
            ldsm4(qh[kc], su32(&Kh[rw * AST + cl]));
        }
    }
    __syncthreads();

    loadTile(kbh, dsm, 0);
    loadTile(vbh, dsm + 2 * AARR, 0);
    CP_COMMIT(); CP_WAIT(0); __syncthreads();

    float oacc[8][4];
#pragma unroll
    for (int nt = 0; nt < 8; nt++)
#pragma unroll
        for (int i = 0; i < 4; i++) oacc[nt][i] = 0.f;
    float mr0 = -1e30f, mr1 = -1e30f, lr0 = 0.f, lr1 = 0.f;

    const uint32_t kla = (lane & 15) * AST * 2 + ((lane >> 4) << 3) * 2;
    const uint32_t vla = ((lane & 7) + ((lane >> 3) & 1) * 8) * AST * 2 +
                         ((lane >> 4) << 3) * 2;

    for (int kt = 0; kt < 16; kt++) {
        const int s = kt & 1;

        // ---- S = Q K^T (reads K[s]) ----
        float sacc[16][4];
#pragma unroll
        for (int nt = 0; nt < 16; nt++)
#pragma unroll
            for (int i = 0; i < 4; i++) sacc[nt][i] = 0.f;

        {
            const uint32_t kb0 = su32(dsm + s * AARR) + kla;
            uint32_t kb[2][4];
            ldsm4(kb[0], kb0);
#pragma unroll
            for (int idx = 0; idx < 32; idx++) {
                const int np = idx >> 2, kc = idx & 3;
                const int cur = idx & 1;
                if (idx < 31) {
                    const int np1 = (idx + 1) >> 2, kc1 = (idx + 1) & 3;
                    ldsm4(kb[cur ^ 1], kb0 + np1 * 16 * AST * 2 + kc1 * 32);
                }
                mmaf16(sacc[np * 2],     qh[kc], kb[cur][0], kb[cur][2]);
                mmaf16(sacc[np * 2 + 1], qh[kc], kb[cur][1], kb[cur][3]);
            }
        }

        if (kt < 15) {
            loadTile(kbh, dsm + (s ^ 1) * AARR, (kt + 1) * 128);
            loadTile(vbh, dsm + (2 + (s ^ 1)) * AARR, (kt + 1) * 128);
            CP_COMMIT();
        }

        // ---- online softmax (base-2 units, packed f16x2 exp2) ----
        float tm0 = -1e30f, tm1 = -1e30f;
#pragma unroll
        for (int nt = 0; nt < 16; nt++) {
            tm0 = fmaxf(tm0, fmaxf(sacc[nt][0], sacc[nt][1]));
            tm1 = fmaxf(tm1, fmaxf(sacc[nt][2], sacc[nt][3]));
        }
        tm0 = fmaxf(tm0, __shfl_xor_sync(0xffffffffu, tm0, 1));
        tm0 = fmaxf(tm0, __shfl_xor_sync(0xffffffffu, tm0, 2));
        tm1 = fmaxf(tm1, __shfl_xor_sync(0xffffffffu, tm1, 1));
        tm1 = fmaxf(tm1, __shfl_xor_sync(0xffffffffu, tm1, 2));

        const float nm0 = fmaxf(mr0, tm0 * C2);
        const float nm1 = fmaxf(mr1, tm1 * C2);
        const float al0 = ex2(mr0 - nm0);
        const float al1 = ex2(mr1 - nm1);
        mr0 = nm0; mr1 = nm1;
#pragma unroll
        for (int nt = 0; nt < 8; nt++) {
            oacc[nt][0] *= al0; oacc[nt][1] *= al0;
            oacc[nt][2] *= al1; oacc[nt][3] *= al1;
        }

        float rs0 = 0.f, rs1 = 0.f;
        uint32_t php[8][4];
#pragma unroll
        for (int j = 0; j < 8; j++) {
            php[j][0] = hex2(pkh(fmaf(sacc[2 * j][0],     C2, -nm0),
                                 fmaf(sacc[2 * j][1],     C2, -nm0)));
            php[j][1] = hex2(pkh(fmaf(sacc[2 * j][2],     C2, -nm1),
                                 fmaf(sacc[2 * j][3],     C2, -nm1)));
            php[j][2] = hex2(pkh(fmaf(sacc[2 * j + 1][0], C2, -nm0),
                                 fmaf(sacc[2 * j + 1][1], C2, -nm0)));
            php[j][3] = hex2(pkh(fmaf(sacc[2 * j + 1][2], C2, -nm1),
                                 fmaf(sacc[2 * j + 1][3], C2, -nm1)));
            const float2 f0 = h2f2(php[j][0]);
            const float2 f1 = h2f2(php[j][1]);
            const float2 f2 = h2f2(php[j][2]);
            const float2 f3 = h2f2(php[j][3]);
            rs0 += (f0.x + f0.y) + (f2.x + f2.y);
            rs1 += (f1.x + f1.y) + (f3.x + f3.y);
        }
        rs0 += __shfl_xor_sync(0xffffffffu, rs0, 1);
        rs0 += __shfl_xor_sync(0xffffffffu, rs0, 2);
        rs1 += __shfl_xor_sync(0xffffffffu, rs1, 1);
        rs1 += __shfl_xor_sync(0xffffffffu, rs1, 2);
        lr0 = lr0 * al0 + rs0;
        lr1 = lr1 * al1 + rs1;

        // ---- O += P V (reads V[s]) ----
        {
            const uint32_t vb0 = su32(dsm + (2 + s) * AARR) + vla;
            uint32_t vb[2][4];
            ldsm4t(vb[0], vb0);
#pragma unroll
            for (int idx = 0; idx < 32; idx++) {
                const int j = idx >> 2, dp = idx & 3;
                const int cur = idx & 1;
                if (idx < 31) {
                    const int j1 = (idx + 1) >> 2, dp1 = (idx + 1) & 3;
                    ldsm4t(vb[cur ^ 1], vb0 + j1 * 16 * AST * 2 + dp1 * 32);
                }
                mmaf16(oacc[dp * 2],     php[j], vb[cur][0], vb[cur][1]);
                mmaf16(oacc[dp * 2 + 1], php[j], vb[cur][2], vb[cur][3]);
            }
        }

        if (kt < 15) { CP_WAIT(0); __syncthreads(); }
    }

    // ---- epilogue: normalize, store fp16 ----
    const float inv0 = 1.f / lr0, inv1 = 1.f / lr1;
    const int g = lane >> 2, tq = lane & 3;
    const size_t r0o = (size_t)(q0 + wid * 16 + g);
#pragma unroll
    for (int nt = 0; nt < 8; nt++) {
        const int col = h * DH_ + nt * 8 + tq * 2;
        *(uint32_t*)&attnh[r0o * D_ + col] =
            pkh(oacc[nt][0] * inv0, oacc[nt][1] * inv0);
        *(uint32_t*)&attnh[(r0o + 8) * D_ + col] =
            pkh(oacc[nt][2] * inv1, oacc[nt][3] * inv1);
    }
}

// ---------------------------------------------------------------------------
// kernel_launch — single stream; PDL chain:
//   P, then per batch b: Q_b (wait iff b==0), A_b (wait), O_b (wait).
// Q_{b>=1} skips its wait (needs only P's output, guaranteed causally via
// Q0.wait(P) and the trigger chain), so it overlaps A_{b-1}/O_{b-1}.
// No streams/events/allocations — graph-capture and mem-checkpoint clean.
// ---------------------------------------------------------------------------
extern "C" void kernel_launch(void* const* d_in, const int* in_sizes, int n_in,
                              void* d_out, int out_size)
{
    const float* x     = (const float*)d_in[0];
    const float* w_qkv = (const float*)d_in[1];
    const float* b_qkv = (const float*)d_in[2];
    const float* w_out = (const float*)d_in[3];
    const float* b_out = (const float*)d_in[4];
    float* out = (float*)d_out;

    __half *xh, *wqh, *woh, *qh, *ah;
    cudaGetSymbolAddress((void**)&xh,  g_x_h);
    cudaGetSymbolAddress((void**)&wqh, g_wqkv_h);
    cudaGetSymbolAddress((void**)&woh, g_wout_h);
    cudaGetSymbolAddress((void**)&qh,  g_qkv_h);
    cudaGetSymbolAddress((void**)&ah,  g_attn_h);

    const int gsmem = NSTG * GSTAGE;  // 81920
    cudaFuncSetAttribute(gemm_f16<true>,
                         cudaFuncAttributeMaxDynamicSharedMemorySize, gsmem);
    cudaFuncSetAttribute(gemm_f16<false>,
                         cudaFuncAttributeMaxDynamicSharedMemorySize, gsmem);
    const int asmem = 4 * AARR;  // 73728
    cudaFuncSetAttribute(attn_f16,
                         cudaFuncAttributeMaxDynamicSharedMemorySize, asmem);

    // PDL launch attribute (shared by all chained launches)
    cudaLaunchAttribute pdl_attr;
    pdl_attr.id = cudaLaunchAttributeProgrammaticStreamSerialization;
    pdl_attr.val.programmaticStreamSerializationAllowed = 1;

    // 0) round all inputs to fp16 (plain launch; Q0's wait covers it)
    presingle_all<<<2048, 256>>>(x, w_qkv, w_out, xh, wqh, woh);

    for (int b = 0; b < B_; b++) {
        const size_t xoff = (size_t)b * T_ * D_;
        const size_t qoff = (size_t)b * T_ * QKV_COLS;

        // 1) QKV projection for batch b (wait only for b==0)
        {
            cudaLaunchConfig_t cfg = {};
            cfg.gridDim = dim3(QKV_COLS / 128, T_ / 128);
            cfg.blockDim = dim3(128);
            cfg.dynamicSmemBytes = gsmem;
            cfg.stream = 0;
            cfg.attrs = &pdl_attr;
            cfg.numAttrs = 1;
            const __half* a = xh + xoff;
            __half* c = qh + qoff;
            float* cf = nullptr;
            int ntot = QKV_COLS, kk = D_, dw = (b == 0) ? 1 : 0;
            cudaLaunchKernelEx(&cfg, gemm_f16<true>,
                               a, (const __half*)wqh, b_qkv, cf, c, ntot, kk, dw);
        }
        // 2) Flash attention for batch b (waits on Q_b)
        {
            cudaLaunchConfig_t cfg = {};
            cfg.gridDim = dim3(T_ / 128, H_);
            cfg.blockDim = dim3(256);
            cfg.dynamicSmemBytes = asmem;
            cfg.stream = 0;
            cfg.attrs = &pdl_attr;
            cfg.numAttrs = 1;
            const __half* q = qh + qoff;
            __half* o = ah + xoff;
            cudaLaunchKernelEx(&cfg, attn_f16, q, o);
        }
        // 3) Output projection for batch b (waits on A_b)
        {
            cudaLaunchConfig_t cfg = {};
            cfg.gridDim = dim3(D_ / 128, T_ / 128);
            cfg.blockDim = dim3(128);
            cfg.dynamicSmemBytes = gsmem;
            cfg.stream = 0;
            cfg.attrs = &pdl_attr;
            cfg.numAttrs = 1;
            const __half* a = ah + xoff;
            float* cf = out + xoff;
            __half* c = nullptr;
            int ntot = D_, kk = D_, dw = 1;
            cudaLaunchKernelEx(&cfg, gemm_f16<false>,
                               a, (const __half*)woh, b_out, cf, c, ntot, kk, dw);
        }
    }
}

// round 16
// speedup vs baseline: 1.2180x; 1.2180x over previous
#include <cuda_runtime.h>
#include <cuda_fp16.h>
#include <math.h>
#include <stdint.h>

#define B_   4
#define T_   2048
#define D_   1024
#define H_   16
#define DH_  64
#define NTOK (B_ * T_)          // 8192
#define QKV_COLS (3 * D_)       // 3072

// ---------------------------------------------------------------------------
// fp16 global scratch (allocation-free rule: __device__ globals)
// ---------------------------------------------------------------------------
__device__ __half g_x_h[(size_t)NTOK * D_];
__device__ __half g_wqkv_h[(size_t)QKV_COLS * D_];
__device__ __half g_wout_h[(size_t)D_ * D_];
__device__ __half g_qkv_h[(size_t)NTOK * QKV_COLS];
__device__ __half g_attn_h[(size_t)NTOK * D_];

// ---------------------------------------------------------------------------
// helpers
// ---------------------------------------------------------------------------
__device__ __forceinline__ uint32_t su32(const void* p) {
    return (uint32_t)__cvta_generic_to_shared(p);
}
__device__ __forceinline__ void ldsm4(uint32_t* r, uint32_t a) {
    asm volatile("ldmatrix.sync.aligned.m8n8.x4.shared.b16 {%0,%1,%2,%3}, [%4];"
        : "=r"(r[0]), "=r"(r[1]), "=r"(r[2]), "=r"(r[3]) : "r"(a));
}
__device__ __forceinline__ void ldsm4t(uint32_t* r, uint32_t a) {
    asm volatile("ldmatrix.sync.aligned.m8n8.x4.trans.shared.b16 {%0,%1,%2,%3}, [%4];"
        : "=r"(r[0]), "=r"(r[1]), "=r"(r[2]), "=r"(r[3]) : "r"(a));
}
__device__ __forceinline__ void mmaf16(float* c, const uint32_t* a,
                                       uint32_t b0, uint32_t b1) {
    asm volatile(
        "mma.sync.aligned.m16n8k16.row.col.f32.f16.f16.f32 "
        "{%0,%1,%2,%3},{%4,%5,%6,%7},{%8,%9},{%0,%1,%2,%3};"
        : "+f"(c[0]), "+f"(c[1]), "+f"(c[2]), "+f"(c[3])
        : "r"(a[0]), "r"(a[1]), "r"(a[2]), "r"(a[3]), "r"(b0), "r"(b1));
}
__device__ __forceinline__ uint32_t pkh(float x, float y) {
    __half2 t = __floats2half2_rn(x, y);
    return *reinterpret_cast<uint32_t*>(&t);
}
__device__ __forceinline__ float ex2(float x) {
    float r;
    asm("ex2.approx.f32 %0, %1;" : "=f"(r) : "f"(x));
    return r;
}
__device__ __forceinline__ uint32_t hex2(uint32_t a) {
    uint32_t r;
    asm("ex2.approx.f16x2 %0, %1;" : "=r"(r) : "r"(a));
    return r;
}
__device__ __forceinline__ float2 h2f2(uint32_t a) {
    __half2 t = *reinterpret_cast<__half2*>(&a);
    return __half22float2(t);
}
__device__ __forceinline__ void cpa16(uint32_t s, const void* g) {
    asm volatile("cp.async.cg.shared.global [%0], [%1], 16;" :: "r"(s), "l"(g));
}
#define CP_COMMIT() asm volatile("cp.async.commit_group;" ::: "memory")
#define CP_WAIT(n)  asm volatile("cp.async.wait_group %0;" :: "n"(n) : "memory")

// PDL intrinsics (base sm_90 PTX; no 'a' suffix needed)
__device__ __forceinline__ void gdc_launch() {
    asm volatile("griddepcontrol.launch_dependents;");
}
__device__ __forceinline__ void gdc_wait() {
    asm volatile("griddepcontrol.wait;" ::: "memory");
}

// ---------------------------------------------------------------------------
// merged presplit: fp32 -> fp16 for x, w_qkv, w_out in one launch
// ---------------------------------------------------------------------------
#define N4_X  (NTOK * D_ / 4)
#define N4_WQ (QKV_COLS * D_ / 4)
#define N4_WO (D_ * D_ / 4)

__global__ void presingle_all(const float* __restrict__ x,
                              const float* __restrict__ wq,
                              const float* __restrict__ wo,
                              __half* __restrict__ xh,
                              __half* __restrict__ wqh,
                              __half* __restrict__ woh)
{
    gdc_launch();   // let QKV's CTAs be placed while we drain
    const int total = N4_X + N4_WQ + N4_WO;
    int i = blockIdx.x * blockDim.x + threadIdx.x;
    const int stride = gridDim.x * blockDim.x;
    for (; i < total; i += stride) {
        const float* src;
        __half* dst;
        int j = i;
        if (j < N4_X)                { src = x;  dst = xh; }
        else if ((j -= N4_X) < N4_WQ){ src = wq; dst = wqh; }
        else                         { j -= N4_WQ; src = wo; dst = woh; }
        float4 v = ((const float4*)src)[j];
        ((uint2*)dst)[j] = make_uint2(pkh(v.x, v.y), pkh(v.z, v.w));
    }
}

// ---------------------------------------------------------------------------
// fp16 GEMM (R12 math + PDL trigger/wait at entry).
// BM=BN=128, BK=32, 128 threads (4 warps 2x2, warp tile 64x64).
// ---------------------------------------------------------------------------
#define GST 40
#define GARR (128 * GST * 2)
#define GSTAGE (2 * GARR)
#define NSTG 4

template<bool WRITE_HALF>
__global__ __launch_bounds__(128, 2)
void gemm_f16(const __half* __restrict__ Ahg, const __half* __restrict__ Bhg,
              const float* __restrict__ bias,
              float* __restrict__ Cf, __half* __restrict__ Ch, int Ntot, int K)
{
    extern __shared__ char dsm[];

    gdc_launch();
    gdc_wait();

    const int tid = threadIdx.x, lane = tid & 31, wid = tid >> 5;
    const int wm = wid & 1, wn = wid >> 1;
    const int row0 = blockIdx.y * 128, col0 = blockIdx.x * 128;

    float acc[4][8][4];
#pragma unroll
    for (int mt = 0; mt < 4; mt++)
#pragma unroll
        for (int nt = 0; nt < 8; nt++)
#pragma unroll
            for (int i = 0; i < 4; i++) acc[mt][nt][i] = 0.f;

    auto prefetch = [&](int it) {
        char* base = dsm + (it & (NSTG - 1)) * GSTAGE;
#pragma unroll
        for (int i = 0; i < 4; i++) {
            const int id = tid + i * 128;
            const int r = id >> 2, c = id & 3;
            const uint32_t so = r * 80 + c * 16;
            cpa16(su32(base + so),        Ahg + (size_t)(row0 + r) * K + it * 32 + c * 8);
            cpa16(su32(base + GARR + so), Bhg + (size_t)(col0 + r) * K + it * 32 + c * 8);
        }
    };

    const int nit = K / 32;
#pragma unroll
    for (int it = 0; it < NSTG - 1; it++) { prefetch(it); CP_COMMIT(); }

    const uint32_t la = ((lane & 15) * GST + ((lane >> 4) << 3)) * 2;
    const uint32_t awo = wm * 64 * GST * 2 + la;
    const uint32_t bwo = GARR + wn * 64 * GST * 2 + la;

    CP_WAIT(NSTG - 2);
    __syncthreads();

    uint32_t fa[2][4][4], fb[2][4][4];
    {
        const uint32_t sbase = su32(dsm);
#pragma unroll
        for (int t = 0; t < 4; t++) ldsm4(fa[0][t], sbase + awo + t * 16 * GST * 2);
#pragma unroll
        for (int t = 0; t < 4; t++) ldsm4(fb[0][t], sbase + bwo + t * 16 * GST * 2);
    }

    for (int it = 0; it < nit; it++) {
        const uint32_t sbase = su32(dsm + (it & (NSTG - 1)) * GSTAGE);

#pragma unroll
        for (int t = 0; t < 4; t++) ldsm4(fa[1][t], sbase + awo + t * 16 * GST * 2 + 32);
#pragma unroll
        for (int t = 0; t < 4; t++) ldsm4(fb[1][t], sbase + bwo + t * 16 * GST * 2 + 32);

#pragma unroll
        for (int mt = 0; mt < 4; mt++)
#pragma unroll
            for (int np = 0; np < 4; np++) {
                mmaf16(acc[mt][np * 2],     fa[0][mt], fb[0][np][0], fb[0][np][2]);
                mmaf16(acc[mt][np * 2 + 1], fa[0][mt], fb[0][np][1], fb[0][np][3]);
            }

        if (it + NSTG - 1 < nit) prefetch(it + NSTG - 1);
        CP_COMMIT();
        CP_WAIT(NSTG - 2);
        __syncthreads();

        if (it + 1 < nit) {
            const uint32_t sb2 = su32(dsm + ((it + 1) & (NSTG - 1)) * GSTAGE);
#pragma unroll
            for (int t = 0; t < 4; t++) ldsm4(fa[0][t], sb2 + awo + t * 16 * GST * 2);
#pragma unroll
            for (int t = 0; t < 4; t++) ldsm4(fb[0][t], sb2 + bwo + t * 16 * GST * 2);
        }

#pragma unroll
        for (int mt = 0; mt < 4; mt++)
#pragma unroll
            for (int np = 0; np < 4; np++) {
                mmaf16(acc[mt][np * 2],     fa[1][mt], fb[1][np][0], fb[1][np][2]);
                mmaf16(acc[mt][np * 2 + 1], fa[1][mt], fb[1][np][1], fb[1][np][3]);
            }
    }

    const int g = lane >> 2, tq = lane & 3;
#pragma unroll
    for (int mt = 0; mt < 4; mt++) {
        const int r = row0 + wm * 64 + mt * 16 + g;
#pragma unroll
        for (int nt = 0; nt < 8; nt++) {
            const int c = col0 + wn * 64 + nt * 8 + tq * 2;
            float2 bi = *(const float2*)(bias + c);
            const float f0 = acc[mt][nt][0] + bi.x, f1 = acc[mt][nt][1] + bi.y;
            const float f2 = acc[mt][nt][2] + bi.x, f3 = acc[mt][nt][3] + bi.y;
            if (WRITE_HALF) {
                *(uint32_t*)&Ch[(size_t)r * Ntot + c]       = pkh(f0, f1);
                *(uint32_t*)&Ch[(size_t)(r + 8) * Ntot + c] = pkh(f2, f3);
            } else {
                *(float2*)(Cf + (size_t)r * Ntot + c)       = make_float2(f0, f1);
                *(float2*)(Cf + (size_t)(r + 8) * Ntot + c) = make_float2(f2, f3);
            }
        }
    }
}

// ---------------------------------------------------------------------------
// Flash attention (R12 math + PDL trigger/wait at entry).
// Full merged grid: (T/128, B*H). K/V double-buffered, ONE barrier per tile.
// ---------------------------------------------------------------------------
#define AST 72
#define AARR (128 * AST * 2)   // 18432 bytes per array
#define C2   0.1803368801f     // (1/sqrt(64)) * log2(e)

__global__ __launch_bounds__(256, 2)
void attn_f16(const __half* __restrict__ qkvh, __half* __restrict__ attnh)
{
    extern __shared__ char dsm[];   // K0 | K1 | V0 | V1

    gdc_launch();
    gdc_wait();

    const int tid = threadIdx.x, lane = tid & 31, wid = tid >> 5;
    const int b = blockIdx.y >> 4, h = blockIdx.y & 15;
    const int q0 = blockIdx.x * 128;

    const size_t hb = (size_t)b * T_ * QKV_COLS + h * DH_;
    const __half* qbh = qkvh + hb;
    const __half* kbh = qbh + D_;
    const __half* vbh = qbh + 2 * D_;

    auto loadTile = [&](const __half* src, char* dstbase, int row_off) {
#pragma unroll
        for (int i = 0; i < 4; i++) {
            const int id = tid + i * 256;
            const int r = id >> 3, c = id & 7;
            const uint32_t so = r * 144 + c * 16;
            const size_t g = (size_t)(row_off + r) * QKV_COLS + c * 8;
            cpa16(su32(dstbase + so), src + g);
        }
    };

    // ---- stage Q into K0, pull fragments ----
    loadTile(qbh, dsm, q0);
    CP_COMMIT(); CP_WAIT(0); __syncthreads();

    uint32_t qh[4][4];
    {
        const __half* Kh = (const __half*)dsm;
#pragma unroll
        for (int kc = 0; kc < 4; kc++) {
            const int rw = wid * 16 + (lane & 15);
            const int cl = kc * 16 + ((lane >> 4) << 3);
            ldsm4(qh[kc], su32(&Kh[rw * AST + cl]));
        }
    }
    __syncthreads();

    loadTile(kbh, dsm, 0);
    loadTile(vbh, dsm + 2 * AARR, 0);
    CP_COMMIT(); CP_WAIT(0); __syncthreads();

    float oacc[8][4];
#pragma unroll
    for (int nt = 0; nt < 8; nt++)
#pragma unroll
        for (int i = 0; i < 4; i++) oacc[nt][i] = 0.f;
    float mr0 = -1e30f, mr1 = -1e30f, lr0 = 0.f, lr1 = 0.f;

    const uint32_t kla = (lane & 15) * AST * 2 + ((lane >> 4) << 3) * 2;
    const uint32_t vla = ((lane & 7) + ((lane >> 3) & 1) * 8) * AST * 2 +
                         ((lane >> 4) << 3) * 2;

    for (int kt = 0; kt < 16; kt++) {
        const int s = kt & 1;

        // ---- S = Q K^T (reads K[s]) ----
        float sacc[16][4];
#pragma unroll
        for (int nt = 0; nt < 16; nt++)
#pragma unroll
            for (int i = 0; i < 4; i++) sacc[nt][i] = 0.f;

        {
            const uint32_t kb0 = su32(dsm + s * AARR) + kla;
            uint32_t kb[2][4];
            ldsm4(kb[0], kb0);
#pragma unroll
            for (int idx = 0; idx < 32; idx++) {
                const int np = idx >> 2, kc = idx & 3;
                const int cur = idx & 1;
                if (idx < 31) {
                    const int np1 = (idx + 1) >> 2, kc1 = (idx + 1) & 3;
                    ldsm4(kb[cur ^ 1], kb0 + np1 * 16 * AST * 2 + kc1 * 32);
                }
                mmaf16(sacc[np * 2],     qh[kc], kb[cur][0], kb[cur][2]);
                mmaf16(sacc[np * 2 + 1], qh[kc], kb[cur][1], kb[cur][3]);
            }
        }

        if (kt < 15) {
            loadTile(kbh, dsm + (s ^ 1) * AARR, (kt + 1) * 128);
            loadTile(vbh, dsm + (2 + (s ^ 1)) * AARR, (kt + 1) * 128);
            CP_COMMIT();
        }

        // ---- online softmax (base-2 units, packed f16x2 exp2) ----
        float tm0 = -1e30f, tm1 = -1e30f;
#pragma unroll
        for (int nt = 0; nt < 16; nt++) {
            tm0 = fmaxf(tm0, fmaxf(sacc[nt][0], sacc[nt][1]));
            tm1 = fmaxf(tm1, fmaxf(sacc[nt][2], sacc[nt][3]));
        }
        tm0 = fmaxf(tm0, __shfl_xor_sync(0xffffffffu, tm0, 1));
        tm0 = fmaxf(tm0, __shfl_xor_sync(0xffffffffu, tm0, 2));
        tm1 = fmaxf(tm1, __shfl_xor_sync(0xffffffffu, tm1, 1));
        tm1 = fmaxf(tm1, __shfl_xor_sync(0xffffffffu, tm1, 2));

        const float nm0 = fmaxf(mr0, tm0 * C2);
        const float nm1 = fmaxf(mr1, tm1 * C2);
        const float al0 = ex2(mr0 - nm0);
        const float al1 = ex2(mr1 - nm1);
        mr0 = nm0; mr1 = nm1;
#pragma unroll
        for (int nt = 0; nt < 8; nt++) {
            oacc[nt][0] *= al0; oacc[nt][1] *= al0;
            oacc[nt][2] *= al1; oacc[nt][3] *= al1;
        }

        float rs0 = 0.f, rs1 = 0.f;
        uint32_t php[8][4];
#pragma unroll
        for (int j = 0; j < 8; j++) {
            php[j][0] = hex2(pkh(fmaf(sacc[2 * j][0],     C2, -nm0),
                                 fmaf(sacc[2 * j][1],     C2, -nm0)));
            php[j][1] = hex2(pkh(fmaf(sacc[2 * j][2],     C2, -nm1),
                                 fmaf(sacc[2 * j][3],     C2, -nm1)));
            php[j][2] = hex2(pkh(fmaf(sacc[2 * j + 1][0], C2, -nm0),
                                 fmaf(sacc[2 * j + 1][1], C2, -nm0)));
            php[j][3] = hex2(pkh(fmaf(sacc[2 * j + 1][2], C2, -nm1),
                                 fmaf(sacc[2 * j + 1][3], C2, -nm1)));
            const float2 f0 = h2f2(php[j][0]);
            const float2 f1 = h2f2(php[j][1]);
            const float2 f2 = h2f2(php[j][2]);
            const float2 f3 = h2f2(php[j][3]);
            rs0 += (f0.x + f0.y) + (f2.x + f2.y);
            rs1 += (f1.x + f1.y) + (f3.x + f3.y);
        }
        rs0 += __shfl_xor_sync(0xffffffffu, rs0, 1);
        rs0 += __shfl_xor_sync(0xffffffffu, rs0, 2);
        rs1 += __shfl_xor_sync(0xffffffffu, rs1, 1);
        rs1 += __shfl_xor_sync(0xffffffffu, rs1, 2);
        lr0 = lr0 * al0 + rs0;
        lr1 = lr1 * al1 + rs1;

        // ---- O += P V (reads V[s]) ----
        {
            const uint32_t vb0 = su32(dsm + (2 + s) * AARR) + vla;
            uint32_t vb[2][4];
            ldsm4t(vb[0], vb0);
#pragma unroll
            for (int idx = 0; idx < 32; idx++) {
                const int j = idx >> 2, dp = idx & 3;
                const int cur = idx & 1;
                if (idx < 31) {
                    const int j1 = (idx + 1) >> 2, dp1 = (idx + 1) & 3;
                    ldsm4t(vb[cur ^ 1], vb0 + j1 * 16 * AST * 2 + dp1 * 32);
                }
                mmaf16(oacc[dp * 2],     php[j], vb[cur][0], vb[cur][1]);
                mmaf16(oacc[dp * 2 + 1], php[j], vb[cur][2], vb[cur][3]);
            }
        }

        if (kt < 15) { CP_WAIT(0); __syncthreads(); }
    }

    // ---- epilogue: normalize, store fp16 ----
    const float inv0 = 1.f / lr0, inv1 = 1.f / lr1;
    const int g = lane >> 2, tq = lane & 3;
    const size_t r0o = (size_t)(b * T_ + q0 + wid * 16 + g);
#pragma unroll
    for (int nt = 0; nt < 8; nt++) {
        const int col = h * DH_ + nt * 8 + tq * 2;
        *(uint32_t*)&attnh[r0o * D_ + col] =
            pkh(oacc[nt][0] * inv0, oacc[nt][1] * inv0);
        *(uint32_t*)&attnh[(r0o + 8) * D_ + col] =
            pkh(oacc[nt][2] * inv1, oacc[nt][3] * inv1);
    }
}

// ---------------------------------------------------------------------------
// kernel_launch — single stream, FULL merged grids (R12 shape), PDL attribute
// on the three big launches so each successor's CTAs are placed while the
// predecessor's last wave drains. No streams/events/allocations.
// ---------------------------------------------------------------------------
extern "C" void kernel_launch(void* const* d_in, const int* in_sizes, int n_in,
                              void* d_out, int out_size)
{
    const float* x     = (const float*)d_in[0];
    const float* w_qkv = (const float*)d_in[1];
    const float* b_qkv = (const float*)d_in[2];
    const float* w_out = (const float*)d_in[3];
    const float* b_out = (const float*)d_in[4];
    float* out = (float*)d_out;

    __half *xh, *wqh, *woh, *qh, *ah;
    cudaGetSymbolAddress((void**)&xh,  g_x_h);
    cudaGetSymbolAddress((void**)&wqh, g_wqkv_h);
    cudaGetSymbolAddress((void**)&woh, g_wout_h);
    cudaGetSymbolAddress((void**)&qh,  g_qkv_h);
    cudaGetSymbolAddress((void**)&ah,  g_attn_h);

    const int gsmem = NSTG * GSTAGE;  // 81920
    cudaFuncSetAttribute(gemm_f16<true>,
                         cudaFuncAttributeMaxDynamicSharedMemorySize, gsmem);
    cudaFuncSetAttribute(gemm_f16<false>,
                         cudaFuncAttributeMaxDynamicSharedMemorySize, gsmem);
    const int asmem = 4 * AARR;  // 73728
    cudaFuncSetAttribute(attn_f16,
                         cudaFuncAttributeMaxDynamicSharedMemorySize, asmem);

    cudaLaunchAttribute pdl_attr;
    pdl_attr.id = cudaLaunchAttributeProgrammaticStreamSerialization;
    pdl_attr.val.programmaticStreamSerializationAllowed = 1;

    // 0) round all inputs to fp16
    presingle_all<<<2048, 256>>>(x, w_qkv, w_out, xh, wqh, woh);

    // 1) QKV projection (full grid, PDL)
    {
        cudaLaunchConfig_t cfg = {};
        cfg.gridDim = dim3(QKV_COLS / 128, NTOK / 128);
        cfg.blockDim = dim3(128);
        cfg.dynamicSmemBytes = gsmem;
        cfg.stream = 0;
        cfg.attrs = &pdl_attr;
        cfg.numAttrs = 1;
        float* cf = nullptr;
        cudaLaunchKernelEx(&cfg, gemm_f16<true>,
                           (const __half*)xh, (const __half*)wqh, b_qkv,
                           cf, (__half*)qh, (int)QKV_COLS, (int)D_);
    }

    // 2) Flash attention (full grid, PDL)
    {
        cudaLaunchConfig_t cfg = {};
        cfg.gridDim = dim3(T_ / 128, B_ * H_);
        cfg.blockDim = dim3(256);
        cfg.dynamicSmemBytes = asmem;
        cfg.stream = 0;
        cfg.attrs = &pdl_attr;
        cfg.numAttrs = 1;
        cudaLaunchKernelEx(&cfg, attn_f16, (const __half*)qh, (__half*)ah);
    }

    // 3) Output projection (full grid, PDL)
    {
        cudaLaunchConfig_t cfg = {};
        cfg.gridDim = dim3(D_ / 128, NTOK / 128);
        cfg.blockDim = dim3(128);
        cfg.dynamicSmemBytes = gsmem;
        cfg.stream = 0;
        cfg.attrs = &pdl_attr;
        cfg.numAttrs = 1;
        __half* c = nullptr;
        cudaLaunchKernelEx(&cfg, gemm_f16<false>,
                           (const __half*)ah, (const __half*)woh, b_out,
                           out, c, (int)D_, (int)D_);
    }
}

// round 17
// speedup vs baseline: 1.2351x; 1.0140x over previous
#include <cuda_runtime.h>
#include <cuda_fp16.h>
#include <math.h>
#include <stdint.h>

#define B_   4
#define T_   2048
#define D_   1024
#define H_   16
#define DH_  64
#define NTOK (B_ * T_)          // 8192
#define QKV_COLS (3 * D_)       // 3072

// ---------------------------------------------------------------------------
// fp16 global scratch + dependency counters (allocation-free: __device__)
// ---------------------------------------------------------------------------
__device__ __half g_x_h[(size_t)NTOK * D_];
__device__ __half g_wqkv_h[(size_t)QKV_COLS * D_];
__device__ __half g_wout_h[(size_t)D_ * D_];
__device__ __half g_qkv_h[(size_t)NTOK * QKV_COLS];
__device__ __half g_attn_h[(size_t)NTOK * D_];

__device__ int g_cnt_qkv[B_];     // per-batch QKV-CTA completion count (384 each)
__device__ int g_cnt_attn[64];    // per-(batch,q-tile) attention completion (16 each)

// ---------------------------------------------------------------------------
// helpers
// ---------------------------------------------------------------------------
__device__ __forceinline__ uint32_t su32(const void* p) {
    return (uint32_t)__cvta_generic_to_shared(p);
}
__device__ __forceinline__ void ldsm4(uint32_t* r, uint32_t a) {
    asm volatile("ldmatrix.sync.aligned.m8n8.x4.shared.b16 {%0,%1,%2,%3}, [%4];"
        : "=r"(r[0]), "=r"(r[1]), "=r"(r[2]), "=r"(r[3]) : "r"(a));
}
__device__ __forceinline__ void ldsm4t(uint32_t* r, uint32_t a) {
    asm volatile("ldmatrix.sync.aligned.m8n8.x4.trans.shared.b16 {%0,%1,%2,%3}, [%4];"
        : "=r"(r[0]), "=r"(r[1]), "=r"(r[2]), "=r"(r[3]) : "r"(a));
}
__device__ __forceinline__ void mmaf16(float* c, const uint32_t* a,
                                       uint32_t b0, uint32_t b1) {
    asm volatile(
        "mma.sync.aligned.m16n8k16.row.col.f32.f16.f16.f32 "
        "{%0,%1,%2,%3},{%4,%5,%6,%7},{%8,%9},{%0,%1,%2,%3};"
        : "+f"(c[0]), "+f"(c[1]), "+f"(c[2]), "+f"(c[3])
        : "r"(a[0]), "r"(a[1]), "r"(a[2]), "r"(a[3]), "r"(b0), "r"(b1));
}
__device__ __forceinline__ uint32_t pkh(float x, float y) {
    __half2 t = __floats2half2_rn(x, y);
    return *reinterpret_cast<uint32_t*>(&t);
}
__device__ __forceinline__ float ex2(float x) {
    float r;
    asm("ex2.approx.f32 %0, %1;" : "=f"(r) : "f"(x));
    return r;
}
__device__ __forceinline__ uint32_t hex2(uint32_t a) {
    uint32_t r;
    asm("ex2.approx.f16x2 %0, %1;" : "=r"(r) : "r"(a));
    return r;
}
__device__ __forceinline__ float2 h2f2(uint32_t a) {
    __half2 t = *reinterpret_cast<__half2*>(&a);
    return __half22float2(t);
}
__device__ __forceinline__ void cpa16(uint32_t s, const void* g) {
    asm volatile("cp.async.cg.shared.global [%0], [%1], 16;" :: "r"(s), "l"(g));
}
#define CP_COMMIT() asm volatile("cp.async.commit_group;" ::: "memory")
#define CP_WAIT(n)  asm volatile("cp.async.wait_group %0;" :: "n"(n) : "memory")

// PDL intrinsics (base sm_90 PTX; no 'a' suffix needed)
__device__ __forceinline__ void gdc_launch() {
    asm volatile("griddepcontrol.launch_dependents;");
}
__device__ __forceinline__ void gdc_wait() {
    asm volatile("griddepcontrol.wait;" ::: "memory");
}

// fine-grained dependency: spin (CTA-wide) until *c >= tgt, acquire
__device__ __forceinline__ void spin_on(const int* c, int tgt) {
    if (threadIdx.x == 0) {
        volatile const int* vc = c;
        while (*vc < tgt) __nanosleep(64);
    }
    __syncthreads();
    __threadfence();
}
// release: all prior writes of all threads visible, then bump counter
__device__ __forceinline__ void signal_done(int* c) {
    __threadfence();
    __syncthreads();
    if (threadIdx.x == 0) atomicAdd(c, 1);
}

// ---------------------------------------------------------------------------
// merged presplit: fp32 -> fp16, plus counter reset (safe: consumers cannot
// place before >=1240 QKV CTAs retire, long after presplit completes)
// ---------------------------------------------------------------------------
#define N4_X  (NTOK * D_ / 4)
#define N4_WQ (QKV_COLS * D_ / 4)
#define N4_WO (D_ * D_ / 4)

__global__ void presingle_all(const float* __restrict__ x,
                              const float* __restrict__ wq,
                              const float* __restrict__ wo,
                              __half* __restrict__ xh,
                              __half* __restrict__ wqh,
                              __half* __restrict__ woh)
{
    gdc_launch();
    if (blockIdx.x == 0 && threadIdx.x < B_ + 64) {
        if (threadIdx.x < B_) g_cnt_qkv[threadIdx.x] = 0;
        else                  g_cnt_attn[threadIdx.x - B_] = 0;
    }
    const int total = N4_X + N4_WQ + N4_WO;
    int i = blockIdx.x * blockDim.x + threadIdx.x;
    const int stride = gridDim.x * blockDim.x;
    for (; i < total; i += stride) {
        const float* src;
        __half* dst;
        int j = i;
        if (j < N4_X)                { src = x;  dst = xh; }
        else if ((j -= N4_X) < N4_WQ){ src = wq; dst = wqh; }
        else                         { j -= N4_WQ; src = wo; dst = woh; }
        float4 v = ((const float4*)src)[i < N4_X ? i : j];
        ((uint2*)dst)[i < N4_X ? i : j] = make_uint2(pkh(v.x, v.y), pkh(v.z, v.w));
    }
}

// ---------------------------------------------------------------------------
// fp16 GEMM (R12 math). MODE 0 = QKV: gdc_wait(presplit) + per-batch signal.
//                       MODE 1 = OUT: spin on attention row-group counter.
// BM=BN=128, BK=32, 128 threads (4 warps 2x2, warp tile 64x64).
// ---------------------------------------------------------------------------
#define GST 40
#define GARR (128 * GST * 2)
#define GSTAGE (2 * GARR)
#define NSTG 4

template<bool WRITE_HALF, int MODE>
__global__ __launch_bounds__(128, 2)
void gemm_f16(const __half* __restrict__ Ahg, const __half* __restrict__ Bhg,
              const float* __restrict__ bias,
              float* __restrict__ Cf, __half* __restrict__ Ch, int Ntot, int K)
{
    extern __shared__ char dsm[];

    gdc_launch();
    if (MODE == 0) gdc_wait();                       // QKV: needs presplit done
    else           spin_on(&g_cnt_attn[blockIdx.y], 16);  // OUT: needs its 16 heads

    const int tid = threadIdx.x, lane = tid & 31, wid = tid >> 5;
    const int wm = wid & 1, wn = wid >> 1;
    const int row0 = blockIdx.y * 128, col0 = blockIdx.x * 128;

    float acc[4][8][4];
#pragma unroll
    for (int mt = 0; mt < 4; mt++)
#pragma unroll
        for (int nt = 0; nt < 8; nt++)
#pragma unroll
            for (int i = 0; i < 4; i++) acc[mt][nt][i] = 0.f;

    auto prefetch = [&](int it) {
        char* base = dsm + (it & (NSTG - 1)) * GSTAGE;
#pragma unroll
        for (int i = 0; i < 4; i++) {
            const int id = tid + i * 128;
            const int r = id >> 2, c = id & 3;
            const uint32_t so = r * 80 + c * 16;
            cpa16(su32(base + so),        Ahg + (size_t)(row0 + r) * K + it * 32 + c * 8);
            cpa16(su32(base + GARR + so), Bhg + (size_t)(col0 + r) * K + it * 32 + c * 8);
        }
    };

    const int nit = K / 32;
#pragma unroll
    for (int it = 0; it < NSTG - 1; it++) { prefetch(it); CP_COMMIT(); }

    const uint32_t la = ((lane & 15) * GST + ((lane >> 4) << 3)) * 2;
    const uint32_t awo = wm * 64 * GST * 2 + la;
    const uint32_t bwo = GARR + wn * 64 * GST * 2 + la;

    CP_WAIT(NSTG - 2);
    __syncthreads();

    uint32_t fa[2][4][4], fb[2][4][4];
    {
        const uint32_t sbase = su32(dsm);
#pragma unroll
        for (int t = 0; t < 4; t++) ldsm4(fa[0][t], sbase + awo + t * 16 * GST * 2);
#pragma unroll
        for (int t = 0; t < 4; t++) ldsm4(fb[0][t], sbase + bwo + t * 16 * GST * 2);
    }

    for (int it = 0; it < nit; it++) {
        const uint32_t sbase = su32(dsm + (it & (NSTG - 1)) * GSTAGE);

#pragma unroll
        for (int t = 0; t < 4; t++) ldsm4(fa[1][t], sbase + awo + t * 16 * GST * 2 + 32);
#pragma unroll
        for (int t = 0; t < 4; t++) ldsm4(fb[1][t], sbase + bwo + t * 16 * GST * 2 + 32);

#pragma unroll
        for (int mt = 0; mt < 4; mt++)
#pragma unroll
            for (int np = 0; np < 4; np++) {
                mmaf16(acc[mt][np * 2],     fa[0][mt], fb[0][np][0], fb[0][np][2]);
                mmaf16(acc[mt][np * 2 + 1], fa[0][mt], fb[0][np][1], fb[0][np][3]);
            }

        if (it + NSTG - 1 < nit) prefetch(it + NSTG - 1);
        CP_COMMIT();
        CP_WAIT(NSTG - 2);
        __syncthreads();

        if (it + 1 < nit) {
            const uint32_t sb2 = su32(dsm + ((it + 1) & (NSTG - 1)) * GSTAGE);
#pragma unroll
            for (int t = 0; t < 4; t++) ldsm4(fa[0][t], sb2 + awo + t * 16 * GST * 2);
#pragma unroll
            for (int t = 0; t < 4; t++) ldsm4(fb[0][t], sb2 + bwo + t * 16 * GST * 2);
        }

#pragma unroll
        for (int mt = 0; mt < 4; mt++)
#pragma unroll
            for (int np = 0; np < 4; np++) {
                mmaf16(acc[mt][np * 2],     fa[1][mt], fb[1][np][0], fb[1][np][2]);
                mmaf16(acc[mt][np * 2 + 1], fa[1][mt], fb[1][np][1], fb[1][np][3]);
            }
    }

    const int g = lane >> 2, tq = lane & 3;
#pragma unroll
    for (int mt = 0; mt < 4; mt++) {
        const int r = row0 + wm * 64 + mt * 16 + g;
#pragma unroll
        for (int nt = 0; nt < 8; nt++) {
            const int c = col0 + wn * 64 + nt * 8 + tq * 2;
            float2 bi = *(const float2*)(bias + c);
            const float f0 = acc[mt][nt][0] + bi.x, f1 = acc[mt][nt][1] + bi.y;
            const float f2 = acc[mt][nt][2] + bi.x, f3 = acc[mt][nt][3] + bi.y;
            if (WRITE_HALF) {
                *(uint32_t*)&Ch[(size_t)r * Ntot + c]       = pkh(f0, f1);
                *(uint32_t*)&Ch[(size_t)(r + 8) * Ntot + c] = pkh(f2, f3);
            } else {
                *(float2*)(Cf + (size_t)r * Ntot + c)       = make_float2(f0, f1);
                *(float2*)(Cf + (size_t)(r + 8) * Ntot + c) = make_float2(f2, f3);
            }
        }
    }

    if (MODE == 0) signal_done(&g_cnt_qkv[blockIdx.y >> 4]);
}

// ---------------------------------------------------------------------------
// Flash attention (R12 math): spins on its batch's QKV counter (384 CTAs),
// signals its (batch, q-tile) group on completion.
// Full merged grid: (T/128, B*H). K/V double-buffered, ONE barrier per tile.
// ---------------------------------------------------------------------------
#define AST 72
#define AARR (128 * AST * 2)   // 18432 bytes per array
#define C2   0.1803368801f     // (1/sqrt(64)) * log2(e)

__global__ __launch_bounds__(256, 2)
void attn_f16(const __half* __restrict__ qkvh, __half* __restrict__ attnh)
{
    extern __shared__ char dsm[];   // K0 | K1 | V0 | V1

    gdc_launch();
    const int b = blockIdx.y >> 4, h = blockIdx.y & 15;
    spin_on(&g_cnt_qkv[b], 384);    // this batch's QKV fully written

    const int tid = threadIdx.x, lane = tid & 31, wid = tid >> 5;
    const int q0 = blockIdx.x * 128;

    const size_t hb = (size_t)b * T_ * QKV_COLS + h * DH_;
    const __half* qbh = qkvh + hb;
    const __half* kbh = qbh + D_;
    const __half* vbh = qbh + 2 * D_;

    auto loadTile = [&](const __half* src, char* dstbase, int row_off) {
#pragma unroll
        for (int i = 0; i < 4; i++) {
            const int id = tid + i * 256;
            const int r = id >> 3, c = id & 7;
            const uint32_t so = r * 144 + c * 16;
            const size_t g = (size_t)(row_off + r) * QKV_COLS + c * 8;
            cpa16(su32(dstbase + so), src + g);
        }
    };

    // ---- stage Q into K0, pull fragments ----
    loadTile(qbh, dsm, q0);
    CP_COMMIT(); CP_WAIT(0); __syncthreads();

    uint32_t qh[4][4];
    {
        const __half* Kh = (const __half*)dsm;
#pragma unroll
        for (int kc = 0; kc < 4; kc++) {
            const int rw = wid * 16 + (lane & 15);
            const int cl = kc * 16 + ((lane >> 4) << 3);
            ldsm4(qh[kc], su32(&Kh[rw * AST + cl]));
        }
    }
    __syncthreads();

    loadTile(kbh, dsm, 0);
    loadTile(vbh, dsm + 2 * AARR, 0);
    CP_COMMIT(); CP_WAIT(0); __syncthreads();

    float oacc[8][4];
#pragma unroll
    for (int nt = 0; nt < 8; nt++)
#pragma unroll
        for (int i = 0; i < 4; i++) oacc[nt][i] = 0.f;
    float mr0 = -1e30f, mr1 = -1e30f, lr0 = 0.f, lr1 = 0.f;

    const uint32_t kla = (lane & 15) * AST * 2 + ((lane >> 4) << 3) * 2;
    const uint32_t vla = ((lane & 7) + ((lane >> 3) & 1) * 8) * AST * 2 +
                         ((lane >> 4) << 3) * 2;

    for (int kt = 0; kt < 16; kt++) {
        const int s = kt & 1;

        // ---- S = Q K^T (reads K[s]) ----
        float sacc[16][4];
#pragma unroll
        for (int nt = 0; nt < 16; nt++)
#pragma unroll
            for (int i = 0; i < 4; i++) sacc[nt][i] = 0.f;

        {
            const uint32_t kb0 = su32(dsm + s * AARR) + kla;
            uint32_t kb[2][4];
            ldsm4(kb[0], kb0);
#pragma unroll
            for (int idx = 0; idx < 32; idx++) {
                const int np = idx >> 2, kc = idx & 3;
                const int cur = idx & 1;
                if (idx < 31) {
                    const int np1 = (idx + 1) >> 2, kc1 = (idx + 1) & 3;
                    ldsm4(kb[cur ^ 1], kb0 + np1 * 16 * AST * 2 + kc1 * 32);
                }
                mmaf16(sacc[np * 2],     qh[kc], kb[cur][0], kb[cur][2]);
                mmaf16(sacc[np * 2 + 1], qh[kc], kb[cur][1], kb[cur][3]);
            }
        }

        if (kt < 15) {
            loadTile(kbh, dsm + (s ^ 1) * AARR, (kt + 1) * 128);
            loadTile(vbh, dsm + (2 + (s ^ 1)) * AARR, (kt + 1) * 128);
            CP_COMMIT();
        }

        // ---- online softmax (base-2 units, packed f16x2 exp2) ----
        float tm0 = -1e30f, tm1 = -1e30f;
#pragma unroll
        for (int nt = 0; nt < 16; nt++) {
            tm0 = fmaxf(tm0, fmaxf(sacc[nt][0], sacc[nt][1]));
            tm1 = fmaxf(tm1, fmaxf(sacc[nt][2], sacc[nt][3]));
        }
        tm0 = fmaxf(tm0, __shfl_xor_sync(0xffffffffu, tm0, 1));
        tm0 = fmaxf(tm0, __shfl_xor_sync(0xffffffffu, tm0, 2));
        tm1 = fmaxf(tm1, __shfl_xor_sync(0xffffffffu, tm1, 1));
        tm1 = fmaxf(tm1, __shfl_xor_sync(0xffffffffu, tm1, 2));

        const float nm0 = fmaxf(mr0, tm0 * C2);
        const float nm1 = fmaxf(mr1, tm1 * C2);
        const float al0 = ex2(mr0 - nm0);
        const float al1 = ex2(mr1 - nm1);
        mr0 = nm0; mr1 = nm1;
#pragma unroll
        for (int nt = 0; nt < 8; nt++) {
            oacc[nt][0] *= al0; oacc[nt][1] *= al0;
            oacc[nt][2] *= al1; oacc[nt][3] *= al1;
        }

        float rs0 = 0.f, rs1 = 0.f;
        uint32_t php[8][4];
#pragma unroll
        for (int j = 0; j < 8; j++) {
            php[j][0] = hex2(pkh(fmaf(sacc[2 * j][0],     C2, -nm0),
                                 fmaf(sacc[2 * j][1],     C2, -nm0)));
            php[j][1] = hex2(pkh(fmaf(sacc[2 * j][2],     C2, -nm1),
                                 fmaf(sacc[2 * j][3],     C2, -nm1)));
            php[j][2] = hex2(pkh(fmaf(sacc[2 * j + 1][0], C2, -nm0),
                                 fmaf(sacc[2 * j + 1][1], C2, -nm0)));
            php[j][3] = hex2(pkh(fmaf(sacc[2 * j + 1][2], C2, -nm1),
                                 fmaf(sacc[2 * j + 1][3], C2, -nm1)));
            const float2 f0 = h2f2(php[j][0]);
            const float2 f1 = h2f2(php[j][1]);
            const float2 f2 = h2f2(php[j][2]);
            const float2 f3 = h2f2(php[j][3]);
            rs0 += (f0.x + f0.y) + (f2.x + f2.y);
            rs1 += (f1.x + f1.y) + (f3.x + f3.y);
        }
        rs0 += __shfl_xor_sync(0xffffffffu, rs0, 1);
        rs0 += __shfl_xor_sync(0xffffffffu, rs0, 2);
        rs1 += __shfl_xor_sync(0xffffffffu, rs1, 1);
        rs1 += __shfl_xor_sync(0xffffffffu, rs1, 2);
        lr0 = lr0 * al0 + rs0;
        lr1 = lr1 * al1 + rs1;

        // ---- O += P V (reads V[s]) ----
        {
            const uint32_t vb0 = su32(dsm + (2 + s) * AARR) + vla;
            uint32_t vb[2][4];
            ldsm4t(vb[0], vb0);
#pragma unroll
            for (int idx = 0; idx < 32; idx++) {
                const int j = idx >> 2, dp = idx & 3;
                const int cur = idx & 1;
                if (idx < 31) {
                    const int j1 = (idx + 1) >> 2, dp1 = (idx + 1) & 3;
                    ldsm4t(vb[cur ^ 1], vb0 + j1 * 16 * AST * 2 + dp1 * 32);
                }
                mmaf16(oacc[dp * 2],     php[j], vb[cur][0], vb[cur][1]);
                mmaf16(oacc[dp * 2 + 1], php[j], vb[cur][2], vb[cur][3]);
            }
        }

        if (kt < 15) { CP_WAIT(0); __syncthreads(); }
    }

    // ---- epilogue: normalize, store fp16 ----
    const float inv0 = 1.f / lr0, inv1 = 1.f / lr1;
    const int g = lane >> 2, tq = lane & 3;
    const size_t r0o = (size_t)(b * T_ + q0 + wid * 16 + g);
#pragma unroll
    for (int nt = 0; nt < 8; nt++) {
        const int col = h * DH_ + nt * 8 + tq * 2;
        *(uint32_t*)&attnh[r0o * D_ + col] =
            pkh(oacc[nt][0] * inv0, oacc[nt][1] * inv0);
        *(uint32_t*)&attnh[(r0o + 8) * D_ + col] =
            pkh(oacc[nt][2] * inv1, oacc[nt][3] * inv1);
    }

    signal_done(&g_cnt_attn[b * 16 + blockIdx.x]);
}

// ---------------------------------------------------------------------------
// kernel_launch — single stream, full merged grids, PDL launches; data
// dependences enforced by device counters (fine-grained tail filling).
// No streams/events/allocations.
// ---------------------------------------------------------------------------
extern "C" void kernel_launch(void* const* d_in, const int* in_sizes, int n_in,
                              void* d_out, int out_size)
{
    const float* x     = (const float*)d_in[0];
    const float* w_qkv = (const float*)d_in[1];
    const float* b_qkv = (const float*)d_in[2];
    const float* w_out = (const float*)d_in[3];
    const float* b_out = (const float*)d_in[4];
    float* out = (float*)d_out;

    __half *xh, *wqh, *woh, *qh, *ah;
    cudaGetSymbolAddress((void**)&xh,  g_x_h);
    cudaGetSymbolAddress((void**)&wqh, g_wqkv_h);
    cudaGetSymbolAddress((void**)&woh, g_wout_h);
    cudaGetSymbolAddress((void**)&qh,  g_qkv_h);
    cudaGetSymbolAddress((void**)&ah,  g_attn_h);

    const int gsmem = NSTG * GSTAGE;  // 81920
    cudaFuncSetAttribute((gemm_f16<true, 0>),
                         cudaFuncAttributeMaxDynamicSharedMemorySize, gsmem);
    cudaFuncSetAttribute((gemm_f16<false, 1>),
                         cudaFuncAttributeMaxDynamicSharedMemorySize, gsmem);
    const int asmem = 4 * AARR;  // 73728
    cudaFuncSetAttribute(attn_f16,
                         cudaFuncAttributeMaxDynamicSharedMemorySize, asmem);

    cudaLaunchAttribute pdl_attr;
    pdl_attr.id = cudaLaunchAttributeProgrammaticStreamSerialization;
    pdl_attr.val.programmaticStreamSerializationAllowed = 1;

    // 0) round all inputs to fp16 + reset counters
    presingle_all<<<2048, 256>>>(x, w_qkv, w_out, xh, wqh, woh);

    // 1) QKV projection (full grid, PDL; gdc_wait on presplit; signals batches)
    {
        cudaLaunchConfig_t cfg = {};
        cfg.gridDim = dim3(QKV_COLS / 128, NTOK / 128);
        cfg.blockDim = dim3(128);
        cfg.dynamicSmemBytes = gsmem;
        cfg.stream = 0;
        cfg.attrs = &pdl_attr;
        cfg.numAttrs = 1;
        float* cf = nullptr;
        cudaLaunchKernelEx(&cfg, gemm_f16<true, 0>,
                           (const __half*)xh, (const __half*)wqh, b_qkv,
                           cf, (__half*)qh, (int)QKV_COLS, (int)D_);
    }

    // 2) Flash attention (full grid, PDL; spins per-batch; signals row groups)
    {
        cudaLaunchConfig_t cfg = {};
        cfg.gridDim = dim3(T_ / 128, B_ * H_);
        cfg.blockDim = dim3(256);
        cfg.dynamicSmemBytes = asmem;
        cfg.stream = 0;
        cfg.attrs = &pdl_attr;
        cfg.numAttrs = 1;
        cudaLaunchKernelEx(&cfg, attn_f16, (const __half*)qh, (__half*)ah);
    }

    // 3) Output projection (full grid, PDL; spins per row group)
    {
        cudaLaunchConfig_t cfg = {};
        cfg.gridDim = dim3(D_ / 128, NTOK / 128);
        cfg.blockDim = dim3(128);
        cfg.dynamicSmemBytes = gsmem;
        cfg.stream = 0;
        cfg.attrs = &pdl_attr;
        cfg.numAttrs = 1;
        __half* c = nullptr;
        cudaLaunchKernelEx(&cfg, gemm_f16<false, 1>,
                           (const __half*)ah, (const __half*)woh, b_out,
                           out, c, (int)D_, (int)D_);
    }
}